// round 6
// baseline (speedup 1.0000x reference)
#include <cuda_runtime.h>
#include <cstdint>

#define T_DIM 256
#define D_DIM 44
#define H_DIM 8
#define NPATHS 8192
#define NGROUPS 1024
#define XGT 16          // timesteps per xg warp-tile
#define PF 4            // recurrence prefetch distance

// scratch
__device__ float g_xg[(size_t)NPATHS * T_DIM * 32];   // [path][t][gate]
__device__ float g_hlast[NPATHS * H_DIM];
__device__ int   g_order[NPATHS];

__device__ __forceinline__ float fast_ex2(float x) {
    float r; asm("ex2.approx.f32 %0, %1;" : "=f"(r) : "f"(x)); return r;
}
__device__ __forceinline__ float fast_rcp(float x) {
    float r; asm("rcp.approx.f32 %0, %1;" : "=f"(r) : "f"(x)); return r;
}
// tanh(x) = 1 - 2/(1 + exp(2x))
__device__ __forceinline__ float tanh_f(float x) {
    float e = fast_ex2(2.8853900817779268f * x);
    return 1.0f - 2.0f * fast_rcp(e + 1.0f);
}

// packed f32x2 helpers
__device__ __forceinline__ void ffma2(unsigned long long& d, unsigned long long a, unsigned long long b) {
    asm("fma.rn.f32x2 %0, %1, %2, %0;" : "+l"(d) : "l"(a), "l"(b));
}
__device__ __forceinline__ unsigned long long mul2(unsigned long long a, unsigned long long b) {
    unsigned long long r; asm("mul.rn.f32x2 %0, %1, %2;" : "=l"(r) : "l"(a), "l"(b)); return r;
}
__device__ __forceinline__ unsigned long long add2(unsigned long long a, unsigned long long b) {
    unsigned long long r; asm("add.rn.f32x2 %0, %1, %2;" : "=l"(r) : "l"(a), "l"(b)); return r;
}
__device__ __forceinline__ float hsum2(unsigned long long v) {
    float lo, hi; asm("mov.b64 {%0,%1}, %2;" : "=f"(lo), "=f"(hi) : "l"(v)); return lo + hi;
}

__device__ __forceinline__ unsigned int smem_u32(const void* p) {
    return (unsigned int)__cvta_generic_to_shared(p);
}
__device__ __forceinline__ void cp16(unsigned int dst, const void* src) {
    asm volatile("cp.async.ca.shared.global [%0], [%1], 16;" :: "r"(dst), "l"(src));
}
#define CP_COMMIT()  asm volatile("cp.async.commit_group;" ::: "memory")
#define CP_WAIT0()   asm volatile("cp.async.wait_group 0;" ::: "memory")

// ─────────────────────────────────────────────────────────────────────────────
// Counting sort by last_idx DESCENDING — parallel scan version (~2-3 us).
// ─────────────────────────────────────────────────────────────────────────────
__global__ void __launch_bounds__(1024)
sort_kernel(const int* __restrict__ last_idx)
{
    __shared__ int cnt[256];
    __shared__ int soff[256];
    __shared__ int wsum[8];
    __shared__ int wpre[8];
    const int tid = threadIdx.x;

    if (tid < 256) cnt[tid] = 0;
    __syncthreads();
    for (int i = tid; i < NPATHS; i += 1024) atomicAdd(&cnt[last_idx[i]], 1);
    __syncthreads();

    // descending exclusive prefix: soff[L] = sum_{L' > L} cnt[L']
    int v = 0;
    if (tid < 256) {
        const int r = tid;                 // r-th bin in descending order
        v = cnt[255 - r];
        #pragma unroll
        for (int d = 1; d < 32; d <<= 1) {
            int n = __shfl_up_sync(0xffffffffu, v, d);
            if ((r & 31) >= d) v += n;     // inclusive warp scan
        }
        if ((r & 31) == 31) wsum[r >> 5] = v;
    }
    __syncthreads();
    if (tid == 0) {
        int run = 0;
        #pragma unroll
        for (int w = 0; w < 8; w++) { wpre[w] = run; run += wsum[w]; }
    }
    __syncthreads();
    if (tid < 256) {
        const int r = tid;
        soff[255 - r] = v - cnt[255 - r] + wpre[r >> 5];   // exclusive
    }
    __syncthreads();
    if (tid < 256) cnt[tid] = 0;
    __syncthreads();

    for (int i = tid; i < NPATHS; i += 1024) {
        const int L = last_idx[i];
        const int pos = soff[L] + atomicAdd(&cnt[L], 1);
        g_order[pos] = i;
    }
}

// ─────────────────────────────────────────────────────────────────────────────
// Stage 1: xg[path][t][gate] = (b_ih+b_hh) + W_ih·x_t for t <= last.
// Block = 128 threads = 4 warps; block owns one path; warp w does tiles
// w, w+4, ... of 16 steps each. Lane owns gate row (weights in regs).
// ─────────────────────────────────────────────────────────────────────────────
__global__ void __launch_bounds__(128, 6)
xg_kernel(const float* __restrict__ x,
          const float* __restrict__ W_ih,
          const float* __restrict__ b_ih,
          const float* __restrict__ b_hh,
          const int* __restrict__ last_idx)
{
    __shared__ float4 sxt[4][XGT * 11];   // per-warp x staging (2816 B each)

    const int path = blockIdx.x;
    const int w    = threadIdx.x >> 5;
    const int lane = threadIdx.x & 31;

    // packed W_ih row for this lane's gate
    unsigned long long wihP[22];
    {
        const ulonglong2* wr = (const ulonglong2*)(W_ih + lane * 44);
        #pragma unroll
        for (int k = 0; k < 11; k++) {
            ulonglong2 vv = wr[k];
            wihP[2*k]   = vv.x;
            wihP[2*k+1] = vv.y;
        }
    }
    const float bias = b_ih[lane] + b_hh[lane];
    unsigned long long biasPk;
    {
        union { unsigned long long u; float2 f; } t; t.f = make_float2(bias, 0.0f);
        biasPk = t.u;
    }

    const int last   = last_idx[path];
    const int ntiles = (last + XGT) / XGT;            // ceil((last+1)/16)
    const float4* xr = (const float4*)(x + (size_t)path * T_DIM * D_DIM);
    float* xgo = g_xg + (size_t)path * T_DIM * 32;

    const unsigned int sb = smem_u32(&sxt[w][0]);

    for (int tile = w; tile < ntiles; tile += 4) {
        const int t0 = tile * XGT;

        // stage 16 steps of x (176 float4) via cp.async
        const float4* src = xr + (size_t)t0 * 11;
        #pragma unroll
        for (int r = 0; r < 6; r++) {
            const int i = lane + r * 32;
            if (i < XGT * 11) cp16(sb + (unsigned int)i * 16, src + i);
        }
        CP_COMMIT();
        CP_WAIT0();
        __syncwarp();

        const int smax = min(XGT, last + 1 - t0);
        for (int s = 0; s < smax; s++) {
            const ulonglong2* xs = (const ulonglong2*)&sxt[w][s * 11];
            unsigned long long a0 = biasPk, a1 = 0ull;
            #pragma unroll
            for (int k = 0; k < 11; k++) {
                ulonglong2 xv = xs[k];
                ffma2(a0, wihP[2*k],   xv.x);
                ffma2(a1, wihP[2*k+1], xv.y);
            }
            xgo[(size_t)(t0 + s) * 32 + lane] = hsum2(add2(a0, a1));
        }
        __syncwarp();   // protect staging buffer before next tile's cp.async
    }
}

// ─────────────────────────────────────────────────────────────────────────────
// Stage 2: recurrence. 1 warp/block, two length-matched paths per warp.
// Reads precomputed xg (coalesced 128B/path/step, prefetched PF steps ahead).
// No smem ring, no wih registers -> 32 blocks/SM.
// ─────────────────────────────────────────────────────────────────────────────
__global__ void __launch_bounds__(32, 32)
rec_kernel(const float* __restrict__ W_hh,
           const int* __restrict__ last_idx)
{
    __shared__ float sh[2][16];   // h broadcast, parity double-buffered

    const int lane = threadIdx.x;
    const int pA = g_order[2 * blockIdx.x];
    const int pB = g_order[2 * blockIdx.x + 1];

    unsigned long long whhP[4];
    {
        const ulonglong2* wr = (const ulonglong2*)(W_hh + lane * 8);
        ulonglong2 v0 = wr[0], v1 = wr[1];
        whhP[0] = v0.x; whhP[1] = v0.y; whhP[2] = v1.x; whhP[3] = v1.y;
    }

    // branchless activation:  act(v) = al + be * rcp(1 + ex2(m*v))
    const bool isg = (lane >= 16) && (lane < 24);
    const float m_act  = isg ?  2.8853900817779268f : -1.4426950408889634f;
    const float al_act = isg ?  1.0f : 0.0f;
    const float be_act = isg ? -2.0f : 1.0f;

    const int lastA = last_idx[pA];
    const int lastB = last_idx[pB];
    const int tmax  = max(lastA, lastB);
    const int jl    = lane & 7;

    const float* xga = g_xg + (size_t)pA * T_DIM * 32 + lane;
    const float* xgb = g_xg + (size_t)pB * T_DIM * 32 + lane;

    // prefetch queues (distance PF=4), clamped addresses
    float qA0, qA1, qA2, qA3, qB0, qB1, qB2, qB3;
    qA0 = __ldg(xga + (size_t)min(0, lastA) * 32);
    qA1 = __ldg(xga + (size_t)min(1, lastA) * 32);
    qA2 = __ldg(xga + (size_t)min(2, lastA) * 32);
    qA3 = __ldg(xga + (size_t)min(3, lastA) * 32);
    qB0 = __ldg(xgb + (size_t)min(0, lastB) * 32);
    qB1 = __ldg(xgb + (size_t)min(1, lastB) * 32);
    qB2 = __ldg(xgb + (size_t)min(2, lastB) * 32);
    qB3 = __ldg(xgb + (size_t)min(3, lastB) * 32);

    unsigned long long hAp[4] = {0ull,0ull,0ull,0ull};
    unsigned long long hBp[4] = {0ull,0ull,0ull,0ull};
    float cA = 0.f, cB = 0.f, hlA = 0.f, hlB = 0.f;

    for (int t = 0; t <= tmax; t++) {
        // gates = xg + W_hh·h   (short packed chain)
        unsigned long long a0A = mul2(whhP[0], hAp[0]);
        unsigned long long a1A = mul2(whhP[1], hAp[1]);
        ffma2(a0A, whhP[2], hAp[2]);
        ffma2(a1A, whhP[3], hAp[3]);
        const float accA = qA0 + hsum2(add2(a0A, a1A));

        unsigned long long a0B = mul2(whhP[0], hBp[0]);
        unsigned long long a1B = mul2(whhP[1], hBp[1]);
        ffma2(a0B, whhP[2], hBp[2]);
        ffma2(a1B, whhP[3], hBp[3]);
        const float accB = qB0 + hsum2(add2(a0B, a1B));

        const float uA = fast_rcp(1.0f + fast_ex2(m_act * accA));
        const float aA = fmaf(be_act, uA, al_act);
        const float uB = fast_rcp(1.0f + fast_ex2(m_act * accB));
        const float aB = fmaf(be_act, uB, al_act);

        const float ivA = __shfl_sync(0xffffffffu, aA, jl);
        const float fvA = __shfl_sync(0xffffffffu, aA, jl + 8);
        const float gvA = __shfl_sync(0xffffffffu, aA, jl + 16);
        const float ovA = __shfl_sync(0xffffffffu, aA, jl + 24);
        const float ivB = __shfl_sync(0xffffffffu, aB, jl);
        const float fvB = __shfl_sync(0xffffffffu, aB, jl + 8);
        const float gvB = __shfl_sync(0xffffffffu, aB, jl + 16);
        const float ovB = __shfl_sync(0xffffffffu, aB, jl + 24);

        const bool okA = (t <= lastA);
        const bool okB = (t <= lastB);
        const float cAn  = fmaf(fvA, cA, ivA * gvA);
        const float cBn  = fmaf(fvB, cB, ivB * gvB);
        const float hlAn = ovA * tanh_f(cAn);
        const float hlBn = ovB * tanh_f(cBn);
        cA  = okA ? cAn  : cA;
        hlA = okA ? hlAn : hlA;
        cB  = okB ? cBn  : cB;
        hlB = okB ? hlBn : hlB;

        // publish h (parity buffer), advance prefetch queues
        if (lane < 16) sh[t & 1][lane] = (lane < 8) ? hlA : hlB;

        qA0 = qA1; qA1 = qA2; qA2 = qA3;
        qB0 = qB1; qB1 = qB2; qB2 = qB3;
        {
            const int tp  = t + PF;
            const int tpa = min(tp, lastA);
            const int tpb = min(tp, lastB);
            qA3 = __ldg(xga + (size_t)tpa * 32);
            qB3 = __ldg(xgb + (size_t)tpb * 32);
        }

        __syncwarp();

        // reload packed h
        {
            const ulonglong2* shp = (const ulonglong2*)&sh[t & 1][0];
            ulonglong2 a01 = shp[0], a23 = shp[1];
            hAp[0] = a01.x; hAp[1] = a01.y; hAp[2] = a23.x; hAp[3] = a23.y;
            ulonglong2 b01 = shp[2], b23 = shp[3];
            hBp[0] = b01.x; hBp[1] = b01.y; hBp[2] = b23.x; hBp[3] = b23.y;
        }
    }

    if (lane < 8)        g_hlast[pA * H_DIM + lane]       = hlA;
    else if (lane < 16)  g_hlast[pB * H_DIM + (lane - 8)] = hlB;
}

// ─────────────────────────────────────────────────────────────────────────────
// Fused finalize: per-group logit (binary-search segment sum) + block softmax.
// ─────────────────────────────────────────────────────────────────────────────
__global__ void __launch_bounds__(NGROUPS)
finalize_kernel(const int* __restrict__ group_ids,
                const float* __restrict__ fc_W,
                const float* __restrict__ fc_b,
                float* __restrict__ out)
{
    __shared__ float warpred[32];
    __shared__ float bc;

    const int g   = threadIdx.x;
    const int wid = g >> 5;
    const int lid = g & 31;

    float w[8];
    #pragma unroll
    for (int j = 0; j < 8; j++) w[j] = fc_W[j];

    int lo = 0, hi = NPATHS;
    while (lo < hi) { int mid = (lo + hi) >> 1; if (group_ids[mid] <  g) lo = mid + 1; else hi = mid; }
    const int start = lo;
    hi = NPATHS;
    while (lo < hi) { int mid = (lo + hi) >> 1; if (group_ids[mid] <= g) lo = mid + 1; else hi = mid; }
    const int end = lo;

    float logit = fc_b[0];
    for (int n = start; n < end; n++) {
        const float4* hp = (const float4*)(g_hlast + n * H_DIM);
        float4 h0 = hp[0], h1 = hp[1];
        float s = h0.x * w[0];
        s = fmaf(h0.y, w[1], s);
        s = fmaf(h0.z, w[2], s);
        s = fmaf(h0.w, w[3], s);
        s = fmaf(h1.x, w[4], s);
        s = fmaf(h1.y, w[5], s);
        s = fmaf(h1.z, w[6], s);
        s = fmaf(h1.w, w[7], s);
        logit += s;
    }

    // block max
    float m = logit;
    #pragma unroll
    for (int off = 16; off > 0; off >>= 1) m = fmaxf(m, __shfl_xor_sync(0xffffffffu, m, off));
    if (lid == 0) warpred[wid] = m;
    __syncthreads();
    if (wid == 0) {
        float v = warpred[lid];
        #pragma unroll
        for (int off = 16; off > 0; off >>= 1) v = fmaxf(v, __shfl_xor_sync(0xffffffffu, v, off));
        if (lid == 0) bc = v;
    }
    __syncthreads();
    const float mx = bc;

    const float e = __expf(logit - mx);

    // block sum
    float s = e;
    #pragma unroll
    for (int off = 16; off > 0; off >>= 1) s += __shfl_xor_sync(0xffffffffu, s, off);
    __syncthreads();
    if (lid == 0) warpred[wid] = s;
    __syncthreads();
    if (wid == 0) {
        float v = warpred[lid];
        #pragma unroll
        for (int off = 16; off > 0; off >>= 1) v += __shfl_xor_sync(0xffffffffu, v, off);
        if (lid == 0) bc = v;
    }
    __syncthreads();

    out[g] = e * fast_rcp(bc);
}

extern "C" void kernel_launch(void* const* d_in, const int* in_sizes, int n_in,
                              void* d_out, int out_size)
{
    const float* x      = (const float*)d_in[0];
    const float* W_ih   = (const float*)d_in[1];
    const float* W_hh   = (const float*)d_in[2];
    const float* b_ih   = (const float*)d_in[3];
    const float* b_hh   = (const float*)d_in[4];
    const float* fc_W   = (const float*)d_in[5];
    const float* fc_b   = (const float*)d_in[6];
    const int*   last_i = (const int*)d_in[7];
    const int*   gids   = (const int*)d_in[8];
    float*       out    = (float*)d_out;

    sort_kernel<<<1, 1024>>>(last_i);
    xg_kernel<<<NPATHS, 128>>>(x, W_ih, b_ih, b_hh, last_i);
    rec_kernel<<<NPATHS / 2, 32>>>(W_hh, last_i);
    finalize_kernel<<<1, NGROUPS>>>(gids, fc_W, fc_b, out);
}

// round 7
// speedup vs baseline: 1.3643x; 1.3643x over previous
#include <cuda_runtime.h>
#include <cstdint>

#define T_DIM 256
#define D_DIM 44
#define H_DIM 8
#define NPATHS 8192
#define NGROUPS 1024
#define RING 4

// scratch
__device__ float g_hlast[NPATHS * H_DIM];
__device__ int   g_order[NPATHS];

__device__ __forceinline__ float fast_ex2(float x) {
    float r; asm("ex2.approx.f32 %0, %1;" : "=f"(r) : "f"(x)); return r;
}
__device__ __forceinline__ float fast_rcp(float x) {
    float r; asm("rcp.approx.f32 %0, %1;" : "=f"(r) : "f"(x)); return r;
}
// tanh(x) = 1 - 2/(1 + exp(2x))
__device__ __forceinline__ float tanh_f(float x) {
    float e = fast_ex2(2.8853900817779268f * x);
    return 1.0f - 2.0f * fast_rcp(e + 1.0f);
}

// packed f32x2 helpers
__device__ __forceinline__ void ffma2(unsigned long long& d, unsigned long long a, unsigned long long b) {
    asm("fma.rn.f32x2 %0, %1, %2, %0;" : "+l"(d) : "l"(a), "l"(b));
}
__device__ __forceinline__ unsigned long long add2(unsigned long long a, unsigned long long b) {
    unsigned long long r; asm("add.rn.f32x2 %0, %1, %2;" : "=l"(r) : "l"(a), "l"(b)); return r;
}
__device__ __forceinline__ float hsum2(unsigned long long v) {
    float lo, hi; asm("mov.b64 {%0,%1}, %2;" : "=f"(lo), "=f"(hi) : "l"(v)); return lo + hi;
}

__device__ __forceinline__ unsigned int smem_u32(const void* p) {
    return (unsigned int)__cvta_generic_to_shared(p);
}
__device__ __forceinline__ void cp16_pred(unsigned int dst, const void* src, bool pred) {
    asm volatile(
        "{ .reg .pred q; setp.ne.u32 q, %2, 0;"
        " @q cp.async.ca.shared.global [%0], [%1], 16; }"
        :: "r"(dst), "l"(src), "r"((int)pred));
}
#define CP_COMMIT() asm volatile("cp.async.commit_group;" ::: "memory")
#define CP_WAIT2()  asm volatile("cp.async.wait_group 2;" ::: "memory")

// ─────────────────────────────────────────────────────────────────────────────
// Counting sort by last_idx DESCENDING (parallel scan, ~3 us).
// ─────────────────────────────────────────────────────────────────────────────
__global__ void __launch_bounds__(1024)
sort_kernel(const int* __restrict__ last_idx)
{
    __shared__ int cnt[256];
    __shared__ int soff[256];
    __shared__ int wsum[8];
    __shared__ int wpre[8];
    const int tid = threadIdx.x;

    if (tid < 256) cnt[tid] = 0;
    __syncthreads();
    for (int i = tid; i < NPATHS; i += 1024) atomicAdd(&cnt[last_idx[i]], 1);
    __syncthreads();

    int v = 0;
    if (tid < 256) {
        const int r = tid;                 // r-th bin in descending order
        v = cnt[255 - r];
        #pragma unroll
        for (int d = 1; d < 32; d <<= 1) {
            int n = __shfl_up_sync(0xffffffffu, v, d);
            if ((r & 31) >= d) v += n;
        }
        if ((r & 31) == 31) wsum[r >> 5] = v;
    }
    __syncthreads();
    if (tid == 0) {
        int run = 0;
        #pragma unroll
        for (int w = 0; w < 8; w++) { wpre[w] = run; run += wsum[w]; }
    }
    __syncthreads();
    if (tid < 256) {
        const int r = tid;
        soff[255 - r] = v - cnt[255 - r] + wpre[r >> 5];
    }
    __syncthreads();
    if (tid < 256) cnt[tid] = 0;
    __syncthreads();

    for (int i = tid; i < NPATHS; i += 1024) {
        const int L = last_idx[i];
        const int pos = soff[L] + atomicAdd(&cnt[L], 1);
        g_order[pos] = i;
    }
}

// ─────────────────────────────────────────────────────────────────────────────
// Fused LSTM: 1 warp/block, two length-matched paths. ONE barrier per iter at
// the top; chain(t) and the x_{t+1} dot live in the same barrier-free block so
// ptxas interleaves the dot into the chain's stall shadows. h via shfl only.
// ─────────────────────────────────────────────────────────────────────────────
__global__ void __launch_bounds__(32, 16)
lstm_kernel(const float* __restrict__ x,
            const float* __restrict__ W_ih,
            const float* __restrict__ W_hh,
            const float* __restrict__ b_ih,
            const float* __restrict__ b_hh,
            const int* __restrict__ last_idx)
{
    __shared__ float4 sx[RING][2][11];   // x ring: [stage][side][11 float4]

    const int lane = threadIdx.x;
    const int pA = g_order[2 * blockIdx.x];
    const int pB = g_order[2 * blockIdx.x + 1];

    // packed W_ih row for this lane's gate
    unsigned long long wihP[22];
    {
        const ulonglong2* wr = (const ulonglong2*)(W_ih + lane * 44);
        #pragma unroll
        for (int k = 0; k < 11; k++) {
            ulonglong2 v = wr[k];
            wihP[2*k]   = v.x;
            wihP[2*k+1] = v.y;
        }
    }
    // scalar W_hh row
    float whh[8];
    {
        const float4* wr = (const float4*)(W_hh + lane * 8);
        float4 v0 = wr[0], v1 = wr[1];
        whh[0]=v0.x; whh[1]=v0.y; whh[2]=v0.z; whh[3]=v0.w;
        whh[4]=v1.x; whh[5]=v1.y; whh[6]=v1.z; whh[7]=v1.w;
    }
    const float bias = b_ih[lane] + b_hh[lane];
    unsigned long long biasPk;
    {
        union { unsigned long long u; float2 f; } t; t.f = make_float2(bias, 0.0f);
        biasPk = t.u;
    }

    // branchless activation:  act(v) = al + be * rcp(1 + ex2(m*v))
    const bool isg = (lane >= 16) && (lane < 24);
    const float m_act  = isg ?  2.8853900817779268f : -1.4426950408889634f;
    const float al_act = isg ?  1.0f : 0.0f;
    const float be_act = isg ? -2.0f : 1.0f;

    const int lastA = last_idx[pA];
    const int lastB = last_idx[pB];
    const int tmax  = max(lastA, lastB);
    const int jl    = lane & 7;

    const float4* xrA = (const float4*)(x + (size_t)pA * T_DIM * D_DIM);
    const float4* xrB = (const float4*)(x + (size_t)pB * T_DIM * D_DIM);

    // loaders: lanes 0-10 -> side A, lanes 16-26 -> side B
    const int  side   = lane >> 4;
    const int  slot   = lane & 15;
    const bool ldr    = slot < 11;
    const float4* myx = side ? xrB : xrA;
    const int  mylast = side ? lastB : lastA;
    const unsigned int sbase  = smem_u32(&sx[0][0][0]);
    const unsigned int mydst0 = (unsigned int)((side * 11 + slot) * 16);

    // prologue: prefetch stages 0..3
    #pragma unroll
    for (int p = 0; p < RING; p++) {
        cp16_pred(sbase + (unsigned int)(p * 352) + mydst0,
                  myx + (size_t)p * 11 + slot,
                  ldr && (p <= mylast));
        CP_COMMIT();
    }

    float hA0=0,hA1=0,hA2=0,hA3=0,hA4=0,hA5=0,hA6=0,hA7=0;
    float hB0=0,hB1=0,hB2=0,hB3=0,hB4=0,hB5=0,hB6=0,hB7=0;
    float cA = 0.f, cB = 0.f, hlA = 0.f, hlB = 0.f;

    // initial xd(0) from stage 0 (stages 0,1 are complete after wait2)
    float xdA, xdB;
    CP_WAIT2();
    __syncwarp();
    {
        const ulonglong2* xsA = (const ulonglong2*)&sx[0][0][0];
        const ulonglong2* xsB = (const ulonglong2*)&sx[0][1][0];
        unsigned long long a0A = biasPk, a1A = 0ull, a0B = biasPk, a1B = 0ull;
        #pragma unroll
        for (int k = 0; k < 11; k++) {
            ulonglong2 xvA = xsA[k];
            ulonglong2 xvB = xsB[k];
            ffma2(a0A, wihP[2*k],   xvA.x);
            ffma2(a1A, wihP[2*k+1], xvA.y);
            ffma2(a0B, wihP[2*k],   xvB.x);
            ffma2(a1B, wihP[2*k+1], xvB.y);
        }
        xdA = hsum2(add2(a0A, a1A));
        xdB = hsum2(add2(a0B, a1B));
    }

    for (int t = 0; t <= tmax; t++) {
        // stage t+1 complete (groups drained to <=2 pending)
        CP_WAIT2();
        __syncwarp();

        // ════ single barrier-free block: dot(t+1) [independent] + chain(t) ════

        // -- dot(t+1): 44 FFMA2 + 22 LDS, fully independent of chain(t) --
        const int stg1 = (t + 1) & (RING - 1);
        const ulonglong2* xsA = (const ulonglong2*)&sx[stg1][0][0];
        const ulonglong2* xsB = (const ulonglong2*)&sx[stg1][1][0];
        unsigned long long a0A = biasPk, a1A = 0ull, a0B = biasPk, a1B = 0ull;
        #pragma unroll
        for (int k = 0; k < 11; k++) {
            ulonglong2 xvA = xsA[k];
            ulonglong2 xvB = xsB[k];
            ffma2(a0A, wihP[2*k],   xvA.x);
            ffma2(a1A, wihP[2*k+1], xvA.y);
            ffma2(a0B, wihP[2*k],   xvB.x);
            ffma2(a1B, wihP[2*k+1], xvB.y);
        }

        // prefetch stage t+4 early (slot t&3; its reads finished in iter t-1)
        const int tp = t + RING;
        cp16_pred(sbase + (unsigned int)((tp & (RING - 1)) * 352) + mydst0,
                  myx + (size_t)tp * 11 + slot,
                  ldr && (tp <= mylast));
        CP_COMMIT();

        // -- chain(t): gates = xd + W_hh·h, activations, update --
        float sA0 = fmaf(whh[0], hA0, xdA);
        float sA1 = whh[1] * hA1;
        sA0 = fmaf(whh[2], hA2, sA0);
        sA1 = fmaf(whh[3], hA3, sA1);
        sA0 = fmaf(whh[4], hA4, sA0);
        sA1 = fmaf(whh[5], hA5, sA1);
        sA0 = fmaf(whh[6], hA6, sA0);
        sA1 = fmaf(whh[7], hA7, sA1);
        const float accA = sA0 + sA1;

        float sB0 = fmaf(whh[0], hB0, xdB);
        float sB1 = whh[1] * hB1;
        sB0 = fmaf(whh[2], hB2, sB0);
        sB1 = fmaf(whh[3], hB3, sB1);
        sB0 = fmaf(whh[4], hB4, sB0);
        sB1 = fmaf(whh[5], hB5, sB1);
        sB0 = fmaf(whh[6], hB6, sB0);
        sB1 = fmaf(whh[7], hB7, sB1);
        const float accB = sB0 + sB1;

        const float uA = fast_rcp(1.0f + fast_ex2(m_act * accA));
        const float aA = fmaf(be_act, uA, al_act);
        const float uB = fast_rcp(1.0f + fast_ex2(m_act * accB));
        const float aB = fmaf(be_act, uB, al_act);

        const float ivA = __shfl_sync(0xffffffffu, aA, jl);
        const float fvA = __shfl_sync(0xffffffffu, aA, jl + 8);
        const float gvA = __shfl_sync(0xffffffffu, aA, jl + 16);
        const float ovA = __shfl_sync(0xffffffffu, aA, jl + 24);
        const float ivB = __shfl_sync(0xffffffffu, aB, jl);
        const float fvB = __shfl_sync(0xffffffffu, aB, jl + 8);
        const float gvB = __shfl_sync(0xffffffffu, aB, jl + 16);
        const float ovB = __shfl_sync(0xffffffffu, aB, jl + 24);

        const bool okA = (t <= lastA);
        const bool okB = (t <= lastB);
        const float cAn  = fmaf(fvA, cA, ivA * gvA);
        const float cBn  = fmaf(fvB, cB, ivB * gvB);
        const float hlAn = ovA * tanh_f(cAn);
        const float hlBn = ovB * tanh_f(cBn);
        cA  = okA ? cAn  : cA;
        hlA = okA ? hlAn : hlA;
        cB  = okB ? cBn  : cB;
        hlB = okB ? hlBn : hlB;

        // h broadcast via shfl (no smem, no extra barrier)
        hA0 = __shfl_sync(0xffffffffu, hlA, 0);
        hA1 = __shfl_sync(0xffffffffu, hlA, 1);
        hA2 = __shfl_sync(0xffffffffu, hlA, 2);
        hA3 = __shfl_sync(0xffffffffu, hlA, 3);
        hA4 = __shfl_sync(0xffffffffu, hlA, 4);
        hA5 = __shfl_sync(0xffffffffu, hlA, 5);
        hA6 = __shfl_sync(0xffffffffu, hlA, 6);
        hA7 = __shfl_sync(0xffffffffu, hlA, 7);
        hB0 = __shfl_sync(0xffffffffu, hlB, 0);
        hB1 = __shfl_sync(0xffffffffu, hlB, 1);
        hB2 = __shfl_sync(0xffffffffu, hlB, 2);
        hB3 = __shfl_sync(0xffffffffu, hlB, 3);
        hB4 = __shfl_sync(0xffffffffu, hlB, 4);
        hB5 = __shfl_sync(0xffffffffu, hlB, 5);
        hB6 = __shfl_sync(0xffffffffu, hlB, 6);
        hB7 = __shfl_sync(0xffffffffu, hlB, 7);

        // collapse next xd (off the recurrence chain)
        xdA = hsum2(add2(a0A, a1A));
        xdB = hsum2(add2(a0B, a1B));
    }

    if (lane < 8)        g_hlast[pA * H_DIM + lane]       = hlA;
    else if (lane < 16)  g_hlast[pB * H_DIM + (lane - 8)] = hlB;
}

// ─────────────────────────────────────────────────────────────────────────────
// Finalize: per-path fc dot -> smem; smem counts + block scan -> group starts;
// smem segment sums; shfl softmax. One 1024-thread block, ~4 us.
// ─────────────────────────────────────────────────────────────────────────────
__global__ void __launch_bounds__(NGROUPS)
finalize_kernel(const int* __restrict__ group_ids,
                const float* __restrict__ fc_W,
                const float* __restrict__ fc_b,
                float* __restrict__ out)
{
    __shared__ float sdot[NPATHS];    // 32 KB
    __shared__ int   scnt[NGROUPS];   // 4 KB
    __shared__ int   sstart[NGROUPS]; // 4 KB
    __shared__ int   wsum[32];
    __shared__ float warpred[32];
    __shared__ float bc;

    const int tid = threadIdx.x;
    const int wid = tid >> 5;
    const int lid = tid & 31;

    float w[8];
    #pragma unroll
    for (int j = 0; j < 8; j++) w[j] = fc_W[j];

    scnt[tid] = 0;
    __syncthreads();

    // per-path dot + group counts
    #pragma unroll
    for (int r = 0; r < NPATHS / NGROUPS; r++) {
        const int i = tid + r * NGROUPS;
        const float4* hp = (const float4*)(g_hlast + i * H_DIM);
        float4 h0 = hp[0], h1 = hp[1];
        float s = h0.x * w[0];
        s = fmaf(h0.y, w[1], s);
        s = fmaf(h0.z, w[2], s);
        s = fmaf(h0.w, w[3], s);
        s = fmaf(h1.x, w[4], s);
        s = fmaf(h1.y, w[5], s);
        s = fmaf(h1.z, w[6], s);
        s = fmaf(h1.w, w[7], s);
        sdot[i] = s;
        atomicAdd(&scnt[group_ids[i]], 1);
    }
    __syncthreads();

    // exclusive scan of scnt over 1024 bins
    const int myc = scnt[tid];
    int inc = myc;
    #pragma unroll
    for (int d = 1; d < 32; d <<= 1) {
        int n = __shfl_up_sync(0xffffffffu, inc, d);
        if (lid >= d) inc += n;
    }
    if (lid == 31) wsum[wid] = inc;
    __syncthreads();
    if (wid == 0) {
        int v = wsum[lid];
        int iv = v;
        #pragma unroll
        for (int d = 1; d < 32; d <<= 1) {
            int n = __shfl_up_sync(0xffffffffu, iv, d);
            if (lid >= d) iv += n;
        }
        wsum[lid] = iv - v;   // exclusive warp prefix
    }
    __syncthreads();
    sstart[tid] = inc - myc + wsum[wid];
    __syncthreads();

    // group logit from contiguous smem range (deterministic order)
    float logit = fc_b[0];
    {
        const int s = sstart[tid];
        const int e = s + myc;
        for (int i = s; i < e; i++) logit += sdot[i];
    }

    // block max
    float m = logit;
    #pragma unroll
    for (int off = 16; off > 0; off >>= 1) m = fmaxf(m, __shfl_xor_sync(0xffffffffu, m, off));
    if (lid == 0) warpred[wid] = m;
    __syncthreads();
    if (wid == 0) {
        float v = warpred[lid];
        #pragma unroll
        for (int off = 16; off > 0; off >>= 1) v = fmaxf(v, __shfl_xor_sync(0xffffffffu, v, off));
        if (lid == 0) bc = v;
    }
    __syncthreads();
    const float mx = bc;

    const float e = __expf(logit - mx);

    // block sum
    float s = e;
    #pragma unroll
    for (int off = 16; off > 0; off >>= 1) s += __shfl_xor_sync(0xffffffffu, s, off);
    __syncthreads();
    if (lid == 0) warpred[wid] = s;
    __syncthreads();
    if (wid == 0) {
        float v = warpred[lid];
        #pragma unroll
        for (int off = 16; off > 0; off >>= 1) v += __shfl_xor_sync(0xffffffffu, v, off);
        if (lid == 0) bc = v;
    }
    __syncthreads();

    out[tid] = e * fast_rcp(bc);
}

extern "C" void kernel_launch(void* const* d_in, const int* in_sizes, int n_in,
                              void* d_out, int out_size)
{
    const float* x      = (const float*)d_in[0];
    const float* W_ih   = (const float*)d_in[1];
    const float* W_hh   = (const float*)d_in[2];
    const float* b_ih   = (const float*)d_in[3];
    const float* b_hh   = (const float*)d_in[4];
    const float* fc_W   = (const float*)d_in[5];
    const float* fc_b   = (const float*)d_in[6];
    const int*   last_i = (const int*)d_in[7];
    const int*   gids   = (const int*)d_in[8];
    float*       out    = (float*)d_out;

    sort_kernel<<<1, 1024>>>(last_i);
    lstm_kernel<<<NPATHS / 2, 32>>>(x, W_ih, W_hh, b_ih, b_hh, last_i);
    finalize_kernel<<<1, NGROUPS>>>(gids, fc_W, fc_b, out);
}